// round 1
// baseline (speedup 1.0000x reference)
#include <cuda_runtime.h>
#include <cuda_bf16.h>

#define BB 16
#define CC 512
#define TT 8192
#define T_TILE 64
#define TILES (TT / T_TILE)      // 128
#define NTHREADS 512
#define SSTRIDE 68               // padded smem row stride (floats): (4*sub+t)%32 covers all banks
#define DIVC 512.0f
#define EPSV 1e-8f

// look-back scratch (device globals: no allocation allowed)
__device__ volatile float g_agg_s[BB * TILES];
__device__ volatile float g_agg_q[BB * TILES];
__device__ volatile float g_pre_s[BB * TILES];
__device__ volatile float g_pre_q[BB * TILES];
__device__ volatile int   g_flag [BB * TILES];

__global__ void init_flags_kernel() {
    int i = blockIdx.x * blockDim.x + threadIdx.x;
    if (i < BB * TILES) g_flag[i] = 0;
}

__global__ void __launch_bounds__(NTHREADS, 1)
newNormal_kernel(const float* __restrict__ x,
                 const float* __restrict__ gains,
                 const float* __restrict__ bias,
                 float* __restrict__ out) {
    extern __shared__ float xs[];                 // [CC][SSTRIDE] tile
    __shared__ float ss[T_TILE], qq[T_TILE];
    __shared__ float meanv[T_TILE], invv[T_TILE];
    __shared__ float ex_s_sh, ex_q_sh;

    const int tile = blockIdx.x;                  // 0..127 (fastest -> ascending bid per chain)
    const int b    = blockIdx.y;                  // 0..15
    const int tid  = threadIdx.x;
    const int t0   = tile * T_TILE;

    const float* xb = x + ((size_t)b * CC) * TT + t0;   // [b][0][t0]

    // ---- Phase 1: stage 128KB tile into smem (float4, 16 rows/thread) ----
    const int col4 = tid & 15;       // float4 column within 64-float row (fixed per thread)
    const int row0 = tid >> 4;       // 0..31
    float4 v[16];
#pragma unroll
    for (int k = 0; k < 16; k++) {
        int c = row0 + 32 * k;
        v[k] = __ldg(((const float4*)(xb + (size_t)c * TT)) + col4);
    }
#pragma unroll
    for (int k = 0; k < 16; k++) {
        int c = row0 + 32 * k;
        *(float4*)(xs + c * SSTRIDE + col4 * 4) = v[k];
    }
    __syncthreads();

    // ---- Phase 2: per-t channel sums (8 threads per t column) ----
    {
        const int t   = tid >> 3;    // 0..63
        const int sub = tid & 7;
        float s = 0.f, q = 0.f;
#pragma unroll 8
        for (int c = sub; c < CC; c += 8) {
            float xv = xs[c * SSTRIDE + t];
            s += xv;
            q = fmaf(xv, xv, q);
        }
#pragma unroll
        for (int d = 4; d >= 1; d >>= 1) {
            s += __shfl_down_sync(0xffffffffu, s, d, 8);
            q += __shfl_down_sync(0xffffffffu, q, d, 8);
        }
        if (sub == 0) { ss[t] = s; qq[t] = q; }
    }
    __syncthreads();

    // ---- Phase 3: inclusive Hillis-Steele scan over the 64 tile sums ----
    for (int d = 1; d < T_TILE; d <<= 1) {
        float as = 0.f, aq = 0.f;
        bool act = (tid < T_TILE) && (tid >= d);
        if (act) { as = ss[tid - d]; aq = qq[tid - d]; }
        __syncthreads();
        if (act) { ss[tid] += as; qq[tid] += aq; }
        __syncthreads();
    }

    // ---- Phase 4: decoupled look-back (thread 0) ----
    if (tid == 0) {
        const int idx = b * TILES + tile;
        const float tot_s = ss[T_TILE - 1];
        const float tot_q = qq[T_TILE - 1];
        float ex_s = 0.f, ex_q = 0.f;
        if (tile == 0) {
            g_pre_s[idx] = tot_s;
            g_pre_q[idx] = tot_q;
            __threadfence();
            g_flag[idx] = 2;
        } else {
            g_agg_s[idx] = tot_s;
            g_agg_q[idx] = tot_q;
            __threadfence();
            g_flag[idx] = 1;
            int p = idx - 1;
            for (;;) {
                int f;
                while ((f = g_flag[p]) == 0) { __nanosleep(20); }
                __threadfence();
                if (f == 2) { ex_s += g_pre_s[p]; ex_q += g_pre_q[p]; break; }
                ex_s += g_agg_s[p];
                ex_q += g_agg_q[p];
                --p;
            }
            g_pre_s[idx] = ex_s + tot_s;
            g_pre_q[idx] = ex_q + tot_q;
            __threadfence();
            g_flag[idx] = 2;
        }
        ex_s_sh = ex_s;
        ex_q_sh = ex_q;
    }
    __syncthreads();

    // ---- Phase 5: mean / rsqrt per t ----
    if (tid < T_TILE) {
        float cs = ex_s_sh + ss[tid];
        float cq = ex_q_sh + qq[tid];
        float dv = 1.0f / ((float)(t0 + tid + 1) * DIVC);
        float m  = cs * dv;
        float var = fmaf(-m, m, cq * dv);
        meanv[tid] = m;
        invv[tid]  = rsqrtf(var + EPSV);
    }
    __syncthreads();

    // ---- Phase 6: normalize from smem, write out ----
    {
        float* ob = out + ((size_t)b * CC) * TT + t0;
        const int tb = col4 * 4;
        const float m0 = meanv[tb + 0], m1 = meanv[tb + 1], m2 = meanv[tb + 2], m3 = meanv[tb + 3];
        const float i0 = invv[tb + 0],  i1 = invv[tb + 1],  i2 = invv[tb + 2],  i3 = invv[tb + 3];
#pragma unroll
        for (int k = 0; k < 16; k++) {
            int c = row0 + 32 * k;
            float4 xv = *(const float4*)(xs + c * SSTRIDE + col4 * 4);
            float gn = __ldg(gains + c);
            float bs = __ldg(bias + c);
            float4 o;
            o.x = fmaf((xv.x - m0) * i0, gn, bs);
            o.y = fmaf((xv.y - m1) * i1, gn, bs);
            o.z = fmaf((xv.z - m2) * i2, gn, bs);
            o.w = fmaf((xv.w - m3) * i3, gn, bs);
            ((float4*)(ob + (size_t)c * TT))[col4] = o;
        }
    }
}

extern "C" void kernel_launch(void* const* d_in, const int* in_sizes, int n_in,
                              void* d_out, int out_size) {
    (void)in_sizes; (void)n_in; (void)out_size;
    const float* x     = (const float*)d_in[0];
    const float* gains = (const float*)d_in[1];
    const float* bias  = (const float*)d_in[2];
    float* out = (float*)d_out;

    const size_t smem_bytes = (size_t)CC * SSTRIDE * sizeof(float);  // 139264
    static int attr_set = 0;
    if (!attr_set) {
        cudaFuncSetAttribute(newNormal_kernel,
                             cudaFuncAttributeMaxDynamicSharedMemorySize,
                             (int)smem_bytes);
        attr_set = 1;
    }

    init_flags_kernel<<<(BB * TILES + 255) / 256, 256>>>();
    dim3 grid(TILES, BB);
    newNormal_kernel<<<grid, NTHREADS, smem_bytes>>>(x, gains, bias, out);
}

// round 2
// speedup vs baseline: 1.7219x; 1.7219x over previous
#include <cuda_runtime.h>
#include <cuda_bf16.h>

#define BB 16
#define CC 512
#define TT 8192
#define T_TILE 32
#define TPB (TT / T_TILE)        // 256 tiles per batch row
#define NTILES (BB * TPB)        // 4096
#define NTHREADS 512
#define GRID_P 148
#define DIVC 512.0f
#define EPSV 1e-8f
#define FULL 0xffffffffu

// one 16B record per tile: {s, q, flag, pad}; flag: 0=empty, 1=agg, 2=inclusive prefix
__device__ float4 g_rec[NTILES];

__global__ void init_rec_kernel() {
    int i = blockIdx.x * blockDim.x + threadIdx.x;
    if (i < NTILES) g_rec[i] = make_float4(0.f, 0.f, 0.f, 0.f);
}

__device__ __forceinline__ float4 ld_rec_vol(const float4* p) {
    float4 r;
    asm volatile("ld.volatile.global.v4.f32 {%0,%1,%2,%3}, [%4];"
                 : "=f"(r.x), "=f"(r.y), "=f"(r.z), "=f"(r.w) : "l"(p));
    return r;
}
__device__ __forceinline__ void st_rec_vol(float4* p, float s, float q, int flag) {
    asm volatile("st.volatile.global.v4.f32 [%0], {%1,%2,%3,%4};"
                 :: "l"(p), "f"(s), "f"(q), "f"(__int_as_float(flag)), "f"(0.f)
                 : "memory");
}

__global__ void __launch_bounds__(NTHREADS, 1)
newNormal_kernel(const float* __restrict__ x,
                 const float* __restrict__ gains,
                 const float* __restrict__ bias,
                 float* __restrict__ out) {
    __shared__ float4 part_s[16][8];
    __shared__ float4 part_q[16][8];
    __shared__ float ts[T_TILE], tq[T_TILE];
    __shared__ float meanv[T_TILE], invv[T_TILE];

    const int tid  = threadIdx.x;
    const int tg   = tid & 7;      // t-group: covers t = 4*tg .. 4*tg+3 within tile
    const int j    = tid >> 3;     // 0..63 ; channels c = j + 64*k, k=0..7
    const int lane = tid & 31;
    const int wid  = tid >> 5;

    // gains/bias for this thread's fixed channel set
    float gn[8], bsv[8];
#pragma unroll
    for (int k = 0; k < 8; k++) {
        gn[k]  = __ldg(gains + j + 64 * k);
        bsv[k] = __ldg(bias  + j + 64 * k);
    }

    float4 cur[8], nxt[8];

    int g = blockIdx.x;
    if (g < NTILES) {
        const int b = g >> 8, tile = g & 255;
        const float* p = x + ((size_t)b * CC + j) * TT + tile * T_TILE + 4 * tg;
#pragma unroll
        for (int k = 0; k < 8; k++)
            cur[k] = __ldg((const float4*)(p + (size_t)(64 * k) * TT));
    }

    for (; g < NTILES; g += GRID_P) {
        const int b    = g >> 8;
        const int tile = g & 255;
        const int t0   = tile * T_TILE;

        // ---- prefetch next tile into nxt (latency hidden behind this iter) ----
        const int gnx = g + GRID_P;
        if (gnx < NTILES) {
            const int b2 = gnx >> 8, tl2 = gnx & 255;
            const float* p = x + ((size_t)b2 * CC + j) * TT + tl2 * T_TILE + 4 * tg;
#pragma unroll
            for (int k = 0; k < 8; k++)
                nxt[k] = __ldg((const float4*)(p + (size_t)(64 * k) * TT));
        }

        // ---- per-thread partial channel sums for its 4 t values ----
        float4 s4 = {0,0,0,0}, q4 = {0,0,0,0};
#pragma unroll
        for (int k = 0; k < 8; k++) {
            float4 v = cur[k];
            s4.x += v.x; s4.y += v.y; s4.z += v.z; s4.w += v.w;
            q4.x = fmaf(v.x, v.x, q4.x); q4.y = fmaf(v.y, v.y, q4.y);
            q4.z = fmaf(v.z, v.z, q4.z); q4.w = fmaf(v.w, v.w, q4.w);
        }
        // reduce over the 4 j-values in this warp (lanes tg, tg+8, tg+16, tg+24)
#pragma unroll
        for (int d = 16; d >= 8; d >>= 1) {
            s4.x += __shfl_down_sync(FULL, s4.x, d); s4.y += __shfl_down_sync(FULL, s4.y, d);
            s4.z += __shfl_down_sync(FULL, s4.z, d); s4.w += __shfl_down_sync(FULL, s4.w, d);
            q4.x += __shfl_down_sync(FULL, q4.x, d); q4.y += __shfl_down_sync(FULL, q4.y, d);
            q4.z += __shfl_down_sync(FULL, q4.z, d); q4.w += __shfl_down_sync(FULL, q4.w, d);
        }
        if (lane < 8) { part_s[wid][lane] = s4; part_q[wid][lane] = q4; }
        __syncthreads();

        // ---- cross-warp reduce: 8 threads sum the 16 warp partials ----
        if (tid < 8) {
            float4 S = {0,0,0,0}, Q = {0,0,0,0};
#pragma unroll
            for (int w = 0; w < 16; w++) {
                float4 a = part_s[w][tid];
                S.x += a.x; S.y += a.y; S.z += a.z; S.w += a.w;
                float4 c = part_q[w][tid];
                Q.x += c.x; Q.y += c.y; Q.z += c.z; Q.w += c.w;
            }
            ts[4*tid+0] = S.x; ts[4*tid+1] = S.y; ts[4*tid+2] = S.z; ts[4*tid+3] = S.w;
            tq[4*tid+0] = Q.x; tq[4*tid+1] = Q.y; tq[4*tid+2] = Q.z; tq[4*tid+3] = Q.w;
        }
        __syncthreads();

        // ---- warp 0: inclusive scan over 32 t, then decoupled look-back ----
        if (wid == 0) {
            float s = ts[lane], q = tq[lane];
#pragma unroll
            for (int d = 1; d < 32; d <<= 1) {
                float a = __shfl_up_sync(FULL, s, d);
                float c = __shfl_up_sync(FULL, q, d);
                if (lane >= d) { s += a; q += c; }
            }
            const float tot_s = __shfl_sync(FULL, s, 31);
            const float tot_q = __shfl_sync(FULL, q, 31);

            float ex_s = 0.f, ex_q = 0.f;
            if (tile == 0) {
                if (lane == 0) st_rec_vol(&g_rec[g], tot_s, tot_q, 2);
            } else {
                if (lane == 0) st_rec_vol(&g_rec[g], tot_s, tot_q, 1);
                const int base = g & ~255;
                int p_hi = g - 1;
                for (;;) {
                    const int p = p_hi - lane;
                    float rs, rq; int f;
                    if (p >= base) {
                        float4 r = ld_rec_vol(&g_rec[p]);
                        rs = r.x; rq = r.y; f = __float_as_int(r.z);
                    } else { rs = 0.f; rq = 0.f; f = 2; }
                    if (__ballot_sync(FULL, f == 0)) { __nanosleep(32); continue; }
                    const unsigned m2 = __ballot_sync(FULL, f == 2);
                    if (m2) {
                        const int l2 = __ffs(m2) - 1;   // closest flag-2 (lane0 = nearest pred)
                        float cs = (lane <= l2) ? rs : 0.f;
                        float cq = (lane <= l2) ? rq : 0.f;
#pragma unroll
                        for (int d = 16; d; d >>= 1) {
                            cs += __shfl_down_sync(FULL, cs, d);
                            cq += __shfl_down_sync(FULL, cq, d);
                        }
                        ex_s += __shfl_sync(FULL, cs, 0);
                        ex_q += __shfl_sync(FULL, cq, 0);
                        break;
                    } else {
                        float cs = rs, cq = rq;
#pragma unroll
                        for (int d = 16; d; d >>= 1) {
                            cs += __shfl_down_sync(FULL, cs, d);
                            cq += __shfl_down_sync(FULL, cq, d);
                        }
                        ex_s += __shfl_sync(FULL, cs, 0);
                        ex_q += __shfl_sync(FULL, cq, 0);
                        p_hi -= 32;
                    }
                }
                if (lane == 0) st_rec_vol(&g_rec[g], ex_s + tot_s, ex_q + tot_q, 2);
            }

            const float cs = ex_s + s;
            const float cq = ex_q + q;
            const float dv = 1.0f / ((float)(t0 + lane + 1) * DIVC);
            const float m  = cs * dv;
            const float var = fmaf(-m, m, cq * dv);
            meanv[lane] = m;
            invv[lane]  = rsqrtf(var + EPSV);
        }
        __syncthreads();

        // ---- normalize from registers, write out ----
        {
            const float4 m4 = *(const float4*)&meanv[4 * tg];
            const float4 i4 = *(const float4*)&invv[4 * tg];
            float* po = out + ((size_t)b * CC + j) * TT + t0 + 4 * tg;
#pragma unroll
            for (int k = 0; k < 8; k++) {
                float4 v = cur[k];
                float4 o;
                o.x = fmaf((v.x - m4.x) * i4.x, gn[k], bsv[k]);
                o.y = fmaf((v.y - m4.y) * i4.y, gn[k], bsv[k]);
                o.z = fmaf((v.z - m4.z) * i4.z, gn[k], bsv[k]);
                o.w = fmaf((v.w - m4.w) * i4.w, gn[k], bsv[k]);
                *(float4*)(po + (size_t)(64 * k) * TT) = o;
            }
        }

        // rotate double buffer
#pragma unroll
        for (int k = 0; k < 8; k++) cur[k] = nxt[k];
    }
}

extern "C" void kernel_launch(void* const* d_in, const int* in_sizes, int n_in,
                              void* d_out, int out_size) {
    (void)in_sizes; (void)n_in; (void)out_size;
    const float* x     = (const float*)d_in[0];
    const float* gains = (const float*)d_in[1];
    const float* bias  = (const float*)d_in[2];
    float* out = (float*)d_out;

    init_rec_kernel<<<(NTILES + 255) / 256, 256>>>();
    newNormal_kernel<<<GRID_P, NTHREADS>>>(x, gains, bias, out);
}